// round 3
// baseline (speedup 1.0000x reference)
#include <cuda_runtime.h>
#include <math.h>

#define BB   4
#define NPTS 4096
#define KNN  16
#define CIN  61
#define INF  64
#define OUTF 128
#define NROW (BB*NPTS)          // 16384
#define NITEM (NROW*KNN)        // 262144

typedef unsigned long long u64;
typedef unsigned int       u32;

// ------------------- device scratch (no allocations allowed) ----------------
__device__ int   g_idx[NITEM];
__device__ float g_feat1[NROW*INF];     // post max+relu, input to fw1
__device__ float g_lin1[NROW*OUTF];     // pre-BN1
__device__ float g_lin2[NROW*OUTF];     // pre-BN2
__device__ float g_part[2*512*256];     // per-block partial sums/sumsq
__device__ float g_bn[2*2*OUTF];        // [stage][a(128), c(128)]

// ---------------- packed fp32x2 helpers (FFMA2 pipe) ------------------------
__device__ __forceinline__ u64 pk2(float a) {
    u64 r; asm("mov.b64 %0,{%1,%1};" : "=l"(r) : "f"(a)); return r;
}
__device__ __forceinline__ u64 pk(float lo, float hi) {
    u64 r; asm("mov.b64 %0,{%1,%2};" : "=l"(r) : "f"(lo), "f"(hi)); return r;
}
__device__ __forceinline__ u64 fma2(u64 a, u64 b, u64 c) {
    u64 d; asm("fma.rn.f32x2 %0,%1,%2,%3;" : "=l"(d) : "l"(a), "l"(b), "l"(c)); return d;
}
__device__ __forceinline__ float2 upk(u64 v) {
    float2 f; asm("mov.b64 {%0,%1},%2;" : "=f"(f.x), "=f"(f.y) : "l"(v)); return f;
}

// ----------------------- profiling alignment nop ----------------------------
__global__ void nop_kernel() {}

// ======================= K1: exact KNN, lane-per-query ======================
// 256 blocks x 64 threads. Each thread owns ONE query and scans all 4096
// candidates of its batch from shared memory (broadcast reads). Exact sorted
// top-16 kept in registers. Strict < on d2 reproduces top_k tie-breaking
// (earlier index wins) because each lane visits j in increasing order.
__global__ __launch_bounds__(64) void knn_kernel(const float* __restrict__ pos) {
    extern __shared__ float sp[];                 // [NPTS*3] interleaved xyz
    const int b  = blockIdx.x >> 6;               // 64 blocks per batch
    const int q  = ((blockIdx.x & 63) << 6) + threadIdx.x;
    const float* pb = pos + (size_t)b * NPTS * 3;
    for (int i = threadIdx.x; i < NPTS*3; i += 64) sp[i] = pb[i];
    __syncthreads();

    const float qx = sp[3*q], qy = sp[3*q+1], qz = sp[3*q+2];
    float bd[KNN]; int bi[KNN];
#pragma unroll
    for (int s = 0; s < KNN; s++) { bd[s] = 3.4e38f; bi[s] = 0; }

    for (int j0 = 0; j0 < NPTS; j0 += 4) {
        float d2v[4];
#pragma unroll
        for (int r = 0; r < 4; r++) {
            const float dx = qx - sp[3*(j0+r)];
            const float dy = qy - sp[3*(j0+r)+1];
            const float dz = qz - sp[3*(j0+r)+2];
            // match XLA rounding: no fma contraction, left-to-right sum
            d2v[r] = __fadd_rn(__fadd_rn(__fmul_rn(dx,dx), __fmul_rn(dy,dy)),
                               __fmul_rn(dz,dz));
        }
#pragma unroll
        for (int r = 0; r < 4; r++) {
            if (d2v[r] < bd[KNN-1]) {
                float d = d2v[r]; int ii = j0 + r;
#pragma unroll
                for (int s = 0; s < KNN; s++) {
                    if (d < bd[s]) {
                        const float td = bd[s]; const int ti = bi[s];
                        bd[s] = d; bi[s] = ii; d = td; ii = ti;
                    }
                }
            }
        }
    }
    const int base = ((b * NPTS + q) << 4);
#pragma unroll
    for (int s = 0; s < KNN; s++) g_idx[base + s] = bi[s];
}

// ============ K2: per-neighbor MLP + weighted max-pool (FFMA2) ==============
__global__ __launch_bounds__(128) void relconv_kernel(
    const float* __restrict__ x, const float* __restrict__ pos,
    const float* __restrict__ rw1, const float* __restrict__ rb1,
    const float* __restrict__ rw2, const float* __restrict__ rb2,
    const float* __restrict__ rw3, const float* __restrict__ rb3) {

    __shared__ __align__(16) float sw1[10*32];
    __shared__ __align__(16) float sb1[32];
    __shared__ __align__(16) float sw2[32*64];
    __shared__ __align__(16) float sb2[64];
    __shared__ __align__(16) float sw3[64*64];
    __shared__ __align__(16) float sb3[64];

    const int tid = threadIdx.x;
    for (int i = tid; i < 320;  i += 128) sw1[i] = rw1[i];
    for (int i = tid; i < 32;   i += 128) sb1[i] = rb1[i];
    for (int i = tid; i < 2048; i += 128) sw2[i] = rw2[i];
    for (int i = tid; i < 64;   i += 128) sb2[i] = rb2[i];
    for (int i = tid; i < 4096; i += 128) sw3[i] = rw3[i];
    for (int i = tid; i < 64;   i += 128) sb3[i] = rb3[i];
    __syncthreads();

    const int item = blockIdx.x * 128 + tid;       // 0..262143
    const int k = item & (KNN-1);
    const int n = (item >> 4) & (NPTS-1);
    const int b = item >> 16;
    const int j = g_idx[item];

    const float* pb = pos + (size_t)b * NPTS * 3;
    const float cx = pb[3*n], cy = pb[3*n+1], cz = pb[3*n+2];
    const float gx = pb[3*j], gy = pb[3*j+1], gz = pb[3*j+2];
    const float rx = gx - cx, ry = gy - cy, rz = gz - cz;
    const float s2 = rx*rx + ry*ry + rz*rz;
    const float dis = (s2 > 0.f) ? sqrtf(s2) : 0.f;

    const float f[10] = {cx, cy, cz, gx, gy, gz, rx, ry, rz, dis};

    const u64* w1p = (const u64*)sw1;
    const u64* w2p = (const u64*)sw2;
    const u64* w3p = (const u64*)sw3;

    // layer1: 10 -> 32 (16 pairs), relu
    u64 h1p[16];
#pragma unroll
    for (int d = 0; d < 16; d++) h1p[d] = ((const u64*)sb1)[d];
#pragma unroll
    for (int c = 0; c < 10; c++) {
        const u64 aa = pk2(f[c]);
#pragma unroll
        for (int d = 0; d < 16; d++) h1p[d] = fma2(aa, w1p[c*16 + d], h1p[d]);
    }
    float h1[32];
#pragma unroll
    for (int d = 0; d < 16; d++) {
        float2 t = upk(h1p[d]);
        h1[2*d]   = fmaxf(t.x, 0.f);
        h1[2*d+1] = fmaxf(t.y, 0.f);
    }

    // layer2: 32 -> 64 (32 pairs), relu
    u64 h2p[32];
#pragma unroll
    for (int d = 0; d < 32; d++) h2p[d] = ((const u64*)sb2)[d];
#pragma unroll
    for (int c = 0; c < 32; c++) {
        const u64 aa = pk2(h1[c]);
#pragma unroll
        for (int d = 0; d < 32; d++) h2p[d] = fma2(aa, w2p[c*32 + d], h2p[d]);
    }
    float h2[64];
#pragma unroll
    for (int d = 0; d < 32; d++) {
        float2 t = upk(h2p[d]);
        h2[2*d]   = fmaxf(t.x, 0.f);
        h2[2*d+1] = fmaxf(t.y, 0.f);
    }

    // layer3: 64 -> 64 (32 pairs), no relu
    u64 wp[32];
#pragma unroll
    for (int d = 0; d < 32; d++) wp[d] = ((const u64*)sb3)[d];
#pragma unroll
    for (int c = 0; c < 64; c++) {
        const u64 aa = pk2(h2[c]);
#pragma unroll
        for (int d = 0; d < 32; d++) wp[d] = fma2(aa, w3p[c*32 + d], wp[d]);
    }

    // weights * feat, warp max over k (16 lanes), relu, store (k==0 lane)
    const float* xr = x + ((size_t)b * NPTS + j) * CIN;
    float* outp = g_feat1 + ((size_t)b * NPTS + n) * INF;
#pragma unroll
    for (int d = 0; d < 32; d++) {
        const float2 t = upk(wp[d]);
        const int ch0 = 2*d, ch1 = 2*d + 1;
        float f0, f1;
        if (ch0 < CIN)       f0 = xr[ch0];
        else if (ch0 == 62)  f0 = gy;
        else                 f0 = gx;
        if (ch1 < CIN)       f1 = xr[ch1];
        else if (ch1 == 61)  f1 = gx;
        else                 f1 = gz;
        float v0 = t.x * f0;
        float v1 = t.y * f1;
#pragma unroll
        for (int off = 8; off >= 1; off >>= 1) {
            v0 = fmaxf(v0, __shfl_xor_sync(0xffffffffu, v0, off));
            v1 = fmaxf(v1, __shfl_xor_sync(0xffffffffu, v1, off));
        }
        if (k == 0) {
            outp[ch0] = fmaxf(v0, 0.f);
            outp[ch1] = fmaxf(v1, 0.f);
        }
    }
}

// ======== K3: GEMM1 [16384,64]@[64,128] + fb1, fused col-stats ==============
__global__ __launch_bounds__(256) void gemm1_kernel(
    const float* __restrict__ fw1, const float* __restrict__ fb1) {
    extern __shared__ float dyn[];
    float* sW    = dyn;                 // 64*128
    float* sAT   = dyn + 8192;          // 64*36 padded transpose
    float* sred  = dyn + 8192 + 2304;   // 8*128
    float* sqred = sred + 1024;         // 8*128
    const int tid = threadIdx.x;
    const int r0  = blockIdx.x * 32;

    for (int i = tid; i < 64*128; i += 256) sW[i] = fw1[i];
    for (int i = tid; i < 32*64; i += 256) {
        const int r = i >> 6, c = i & 63;
        sAT[c*36 + r] = g_feat1[(size_t)(r0 + r) * INF + c];
    }
    __syncthreads();

    const int cg = tid & 31;   // 4 cols at 4*cg
    const int rg = tid >> 5;   // 4 rows at 4*rg
    const float4 fb = reinterpret_cast<const float4*>(fb1)[cg];
    u64 accp[4][2];
#pragma unroll
    for (int i = 0; i < 4; i++) { accp[i][0] = pk(fb.x, fb.y); accp[i][1] = pk(fb.z, fb.w); }

    const u64* sWp = (const u64*)sW;
#pragma unroll 4
    for (int kk = 0; kk < 64; kk++) {
        const float4 a = *reinterpret_cast<const float4*>(&sAT[kk*36 + 4*rg]);
        const u64 w0 = sWp[(kk*128 + 4*cg) >> 1];
        const u64 w1 = sWp[((kk*128 + 4*cg) >> 1) + 1];
        const float av[4] = {a.x, a.y, a.z, a.w};
#pragma unroll
        for (int i = 0; i < 4; i++) {
            const u64 aa = pk2(av[i]);
            accp[i][0] = fma2(aa, w0, accp[i][0]);
            accp[i][1] = fma2(aa, w1, accp[i][1]);
        }
    }
    float s[4] = {0,0,0,0}, sq[4] = {0,0,0,0};
#pragma unroll
    for (int i = 0; i < 4; i++) {
        const float2 lo = upk(accp[i][0]), hi = upk(accp[i][1]);
        float4 o = make_float4(lo.x, lo.y, hi.x, hi.y);
        *reinterpret_cast<float4*>(&g_lin1[(size_t)(r0 + 4*rg + i) * OUTF + 4*cg]) = o;
        s[0] += o.x; s[1] += o.y; s[2] += o.z; s[3] += o.w;
        sq[0] = fmaf(o.x,o.x,sq[0]); sq[1] = fmaf(o.y,o.y,sq[1]);
        sq[2] = fmaf(o.z,o.z,sq[2]); sq[3] = fmaf(o.w,o.w,sq[3]);
    }
#pragma unroll
    for (int qq = 0; qq < 4; qq++) { sred[rg*128 + 4*cg + qq] = s[qq]; sqred[rg*128 + 4*cg + qq] = sq[qq]; }
    __syncthreads();
    if (tid < 128) {
        float a = 0.f, v = 0.f;
#pragma unroll
        for (int r = 0; r < 8; r++) { a += sred[r*128 + tid]; v += sqred[r*128 + tid]; }
        g_part[blockIdx.x*256 + tid]       = a;
        g_part[blockIdx.x*256 + 128 + tid] = v;
    }
}

// ==== K4: GEMM2 with BN1+relu on load, [16384,128]@[128,128]+fb2, stats =====
__global__ __launch_bounds__(256) void gemm2_kernel(
    const float* __restrict__ fw2, const float* __restrict__ fb2) {
    extern __shared__ float dyn[];
    float* sW    = dyn;                  // 128*128
    float* sAT   = dyn + 16384;          // 128*36
    float* sred  = dyn + 16384 + 4608;   // 8*128
    float* sqred = sred + 1024;
    const int tid = threadIdx.x;
    const int r0  = blockIdx.x * 32;

    for (int i = tid; i < 128*128; i += 256) sW[i] = fw2[i];
    const float* bn = g_bn;       // stage 0
    for (int i = tid; i < 32*128; i += 256) {
        const int r = i >> 7, c = i & 127;
        float v = g_lin1[(size_t)(r0 + r) * OUTF + c];
        v = fmaf(v, bn[c], bn[128 + c]);
        sAT[c*36 + r] = fmaxf(v, 0.f);
    }
    __syncthreads();

    const int cg = tid & 31;
    const int rg = tid >> 5;
    const float4 fb = reinterpret_cast<const float4*>(fb2)[cg];
    u64 accp[4][2];
#pragma unroll
    for (int i = 0; i < 4; i++) { accp[i][0] = pk(fb.x, fb.y); accp[i][1] = pk(fb.z, fb.w); }

    const u64* sWp = (const u64*)sW;
#pragma unroll 4
    for (int kk = 0; kk < 128; kk++) {
        const float4 a = *reinterpret_cast<const float4*>(&sAT[kk*36 + 4*rg]);
        const u64 w0 = sWp[(kk*128 + 4*cg) >> 1];
        const u64 w1 = sWp[((kk*128 + 4*cg) >> 1) + 1];
        const float av[4] = {a.x, a.y, a.z, a.w};
#pragma unroll
        for (int i = 0; i < 4; i++) {
            const u64 aa = pk2(av[i]);
            accp[i][0] = fma2(aa, w0, accp[i][0]);
            accp[i][1] = fma2(aa, w1, accp[i][1]);
        }
    }
    float s[4] = {0,0,0,0}, sq[4] = {0,0,0,0};
#pragma unroll
    for (int i = 0; i < 4; i++) {
        const float2 lo = upk(accp[i][0]), hi = upk(accp[i][1]);
        float4 o = make_float4(lo.x, lo.y, hi.x, hi.y);
        *reinterpret_cast<float4*>(&g_lin2[(size_t)(r0 + 4*rg + i) * OUTF + 4*cg]) = o;
        s[0] += o.x; s[1] += o.y; s[2] += o.z; s[3] += o.w;
        sq[0] = fmaf(o.x,o.x,sq[0]); sq[1] = fmaf(o.y,o.y,sq[1]);
        sq[2] = fmaf(o.z,o.z,sq[2]); sq[3] = fmaf(o.w,o.w,sq[3]);
    }
#pragma unroll
    for (int qq = 0; qq < 4; qq++) { sred[rg*128 + 4*cg + qq] = s[qq]; sqred[rg*128 + 4*cg + qq] = sq[qq]; }
    __syncthreads();
    if (tid < 128) {
        float a = 0.f, v = 0.f;
#pragma unroll
        for (int r = 0; r < 8; r++) { a += sred[r*128 + tid]; v += sqred[r*128 + tid]; }
        g_part[512*256 + blockIdx.x*256 + tid]       = a;
        g_part[512*256 + blockIdx.x*256 + 128 + tid] = v;
    }
}

// ======== finalize BN coefficients (parallelized: 1024 threads) =============
__global__ __launch_bounds__(1024) void finstats_kernel(
    int sel, const float* __restrict__ gamma, const float* __restrict__ beta) {
    __shared__ float red[4*256];
    __shared__ float tot[256];
    const float* part = g_part + sel * (512*256);
    float* bn = g_bn + sel * (2*OUTF);
    const int t = threadIdx.x;
    const int c = t & 255;
    const int g = t >> 8;               // 4 groups of 128 rows each
    float s = 0.f;
    const int rbeg = g * 128;
#pragma unroll 4
    for (int i = 0; i < 128; i++) s += part[(rbeg + i)*256 + c];
    red[g*256 + c] = s;
    __syncthreads();
    if (t < 256) tot[t] = (red[t] + red[256 + t]) + (red[512 + t] + red[768 + t]);
    __syncthreads();
    if (t < 128) {
        const float inv_n = 1.f / (float)NROW;
        const float m  = tot[t] * inv_n;
        const float v  = tot[128 + t] * inv_n - m * m;
        const float rs = rsqrtf(v + 1e-5f);
        const float a  = rs * gamma[t];
        bn[t]       = a;
        bn[128 + t] = beta[t] - m * a;
    }
}

// ===================== K7: final BN2 -> output ==============================
__global__ __launch_bounds__(1024) void final_kernel(float* __restrict__ out) {
    const int i = blockIdx.x * 1024 + threadIdx.x;   // 0..2097151
    const int c = i & 127;
    const float* bn = g_bn + 2*OUTF;                 // stage 1
    out[i] = fmaf(g_lin2[i], bn[c], bn[128 + c]);
}

// ============================================================================
extern "C" void kernel_launch(void* const* d_in, const int* in_sizes, int n_in,
                              void* d_out, int out_size) {
    (void)in_sizes; (void)n_in; (void)out_size;
    const float* x   = (const float*)d_in[0];
    const float* pos = (const float*)d_in[1];
    const float* rw1 = (const float*)d_in[2];
    const float* rb1 = (const float*)d_in[3];
    const float* rw2 = (const float*)d_in[4];
    const float* rb2 = (const float*)d_in[5];
    const float* rw3 = (const float*)d_in[6];
    const float* rb3 = (const float*)d_in[7];
    const float* fw1 = (const float*)d_in[8];
    const float* fb1 = (const float*)d_in[9];
    const float* g1  = (const float*)d_in[10];
    const float* b1  = (const float*)d_in[11];
    const float* fw2 = (const float*)d_in[12];
    const float* fb2 = (const float*)d_in[13];
    const float* g2  = (const float*)d_in[14];
    const float* b2  = (const float*)d_in[15];
    float* out = (float*)d_out;

    // 5 nops so the ncu capture (-s 5 -c 1) lands on knn_kernel.
    nop_kernel<<<1, 32>>>();
    nop_kernel<<<1, 32>>>();
    nop_kernel<<<1, 32>>>();
    nop_kernel<<<1, 32>>>();
    nop_kernel<<<1, 32>>>();

    const int smem_knn = NPTS * 3 * 4;   // 49152 B
    cudaFuncSetAttribute(knn_kernel, cudaFuncAttributeMaxDynamicSharedMemorySize, smem_knn);
    knn_kernel<<<256, 64, smem_knn>>>(pos);

    relconv_kernel<<<NITEM/128, 128>>>(x, pos, rw1, rb1, rw2, rb2, rw3, rb3);

    const int smem1 = (8192 + 2304 + 2048) * 4;
    cudaFuncSetAttribute(gemm1_kernel, cudaFuncAttributeMaxDynamicSharedMemorySize, smem1);
    gemm1_kernel<<<NROW/32, 256, smem1>>>(fw1, fb1);
    finstats_kernel<<<1, 1024>>>(0, g1, b1);

    const int smem2 = (16384 + 4608 + 2048) * 4;
    cudaFuncSetAttribute(gemm2_kernel, cudaFuncAttributeMaxDynamicSharedMemorySize, smem2);
    gemm2_kernel<<<NROW/32, 256, smem2>>>(fw2, fb2);
    finstats_kernel<<<1, 1024>>>(1, g2, b2);

    final_kernel<<<2097152/1024, 1024>>>(out);
}

// round 5
// speedup vs baseline: 1.5470x; 1.5470x over previous
#include <cuda_runtime.h>
#include <math.h>

#define BB   4
#define NPTS 4096
#define KNN  16
#define CIN  61
#define INF  64
#define OUTF 128
#define NROW (BB*NPTS)          // 16384
#define NITEM (NROW*KNN)        // 262144

typedef unsigned long long u64;
typedef unsigned int       u32;

// ------------------- device scratch (no allocations allowed) ----------------
__device__ int   g_idx[NITEM];
__device__ float g_feat1[NROW*INF];
__device__ float g_lin1[NROW*OUTF];
__device__ float g_lin2[NROW*OUTF];
__device__ float g_part[2*512*256];
__device__ float g_bn[2*2*OUTF];

// ---------------- packed fp32x2 helpers (FFMA2 pipe) ------------------------
__device__ __forceinline__ u64 pk2(float a) {
    u64 r; asm("mov.b64 %0,{%1,%1};" : "=l"(r) : "f"(a)); return r;
}
__device__ __forceinline__ u64 pk(float lo, float hi) {
    u64 r; asm("mov.b64 %0,{%1,%2};" : "=l"(r) : "f"(lo), "f"(hi)); return r;
}
__device__ __forceinline__ u64 fma2(u64 a, u64 b, u64 c) {
    u64 d; asm("fma.rn.f32x2 %0,%1,%2,%3;" : "=l"(d) : "l"(a), "l"(b), "l"(c)); return d;
}
__device__ __forceinline__ float2 upk(u64 v) {
    float2 f; asm("mov.b64 {%0,%1},%2;" : "=f"(f.x), "=f"(f.y) : "l"(v)); return f;
}

// ----------------------- profiling alignment nop ----------------------------
__global__ void nop_kernel() {}

// ======================= K1: exact KNN via radix-bin select =================
// Block = 256 threads handles 8 queries of one batch sequentially.
__global__ __launch_bounds__(256) void knn_kernel(const float* __restrict__ pos) {
    extern __shared__ float sm[];
    float* sp    = sm;                       // [NPTS*3] interleaved
    u32*   sdist = (u32*)(sm + NPTS*3);      // [NPTS]
    u32*   hist  = sdist + NPTS;             // [2048]
    u32*   swarp = hist + 2048;              // [8]
    u32*   listv = swarp + 8;                // [256]
    int*   listj = (int*)(listv + 256);      // [256]
    int*   outj  = listj + 256;              // [16]
    int*   ctl   = outj + 16;                // [4]

    const int tid  = threadIdx.x;
    const int lane = tid & 31;
    const int wid  = tid >> 5;
    const int b    = blockIdx.x >> 9;
    const int q0   = (blockIdx.x & 511) * 8;
    const float* pb = pos + (size_t)b * NPTS * 3;

    for (int i = tid; i < NPTS*3; i += 256) sp[i] = pb[i];
    __syncthreads();

    for (int qi = 0; qi < 8; qi++) {
        const int q = q0 + qi;
        for (int i = tid; i < 2048; i += 256) hist[i] = 0u;
        if (tid == 0) { ctl[0] = 0; ctl[1] = 0; }
        __syncthreads();

        const float qx = sp[3*q], qy = sp[3*q+1], qz = sp[3*q+2];
#pragma unroll
        for (int t = 0; t < 16; t++) {
            const int j = tid + 256*t;
            const float dx = qx - sp[3*j];
            const float dy = qy - sp[3*j+1];
            const float dz = qz - sp[3*j+2];
            // match XLA rounding: no fma contraction, left-to-right sum
            const float d2 = __fadd_rn(__fadd_rn(__fmul_rn(dx,dx), __fmul_rn(dy,dy)),
                                       __fmul_rn(dz,dz));
            const u32 u = __float_as_uint(d2);
            sdist[j] = u;
            atomicAdd(&hist[u >> 21], 1u);
        }
        __syncthreads();

        // prefix over 256 chunks of 8 bins: warp shfl scan + cross-warp fixup
        u32 part = 0;
#pragma unroll
        for (int k2 = 0; k2 < 8; k2++) part += hist[tid*8 + k2];
        u32 v = part;
#pragma unroll
        for (int off = 1; off < 32; off <<= 1) {
            u32 nb = __shfl_up_sync(0xffffffffu, v, off);
            if (lane >= off) v += nb;
        }
        if (lane == 31) swarp[wid] = v;
        __syncthreads();
        u32 base = 0;
#pragma unroll
        for (int w = 0; w < 8; w++) base += (w < wid) ? swarp[w] : 0u;
        const u32 incl = base + v, excl = incl - part;
        if (excl < 16u && incl >= 16u) {
            u32 c = excl;
#pragma unroll
            for (int k2 = 0; k2 < 8; k2++) {
                const u32 h = hist[tid*8 + k2];
                if (c < 16u && c + h >= 16u) { ctl[2] = tid*8 + k2; ctl[3] = (int)c; break; }
                c += h;
            }
        }
        __syncthreads();
        const u32 bstar = (u32)ctl[2];
        const int Lb    = ctl[3];

        // gather: strictly-below bin -> in top-16 (set order free);
        // equal-bin -> candidate list for exact lexicographic select
#pragma unroll
        for (int t = 0; t < 16; t++) {
            const int j = tid + 256*t;
            const u32 u = sdist[j];
            const u32 key = u >> 21;
            if (key < bstar) { int p = atomicAdd(&ctl[0], 1); outj[p] = j; }
            else if (key == bstar) {
                int p = atomicAdd(&ctl[1], 1);
                if (p < 256) { listv[p] = u; listj[p] = j; }
            }
        }
        __syncthreads();

        // warp 0 selects (16-Lb) smallest (value,index) pairs from bin list
        if (tid < 32) {
            const int need = 16 - Lb;
            const int cnt  = min(ctl[1], 256);
            for (int r = 0; r < need; r++) {
                u64 best = ~0ull;
                for (int i = tid; i < cnt; i += 32) {
                    u64 k = ((u64)listv[i] << 32) | (u32)listj[i];
                    if (k < best) best = k;
                }
#pragma unroll
                for (int off = 16; off; off >>= 1) {
                    u64 o = __shfl_xor_sync(0xffffffffu, best, off);
                    if (o < best) best = o;
                }
                for (int i = tid; i < cnt; i += 32) {
                    u64 k = ((u64)listv[i] << 32) | (u32)listj[i];
                    if (k == best) listv[i] = 0xFFFFFFFFu;
                }
                if (tid == 0) outj[Lb + r] = (int)(best & 0xFFFFFFFFull);
                __syncwarp();
            }
        }
        __syncthreads();
        if (tid < 16) g_idx[((b*NPTS + q) << 4) + tid] = outj[tid];
        __syncthreads();
    }
}

// ============ K2: per-neighbor MLP + weighted max-pool (FFMA2) ==============
__global__ __launch_bounds__(128) void relconv_kernel(
    const float* __restrict__ x, const float* __restrict__ pos,
    const float* __restrict__ rw1, const float* __restrict__ rb1,
    const float* __restrict__ rw2, const float* __restrict__ rb2,
    const float* __restrict__ rw3, const float* __restrict__ rb3) {

    __shared__ __align__(16) float sw1[10*32];
    __shared__ __align__(16) float sb1[32];
    __shared__ __align__(16) float sw2[32*64];
    __shared__ __align__(16) float sb2[64];
    __shared__ __align__(16) float sw3[64*64];
    __shared__ __align__(16) float sb3[64];

    const int tid = threadIdx.x;
    for (int i = tid; i < 320;  i += 128) sw1[i] = rw1[i];
    for (int i = tid; i < 32;   i += 128) sb1[i] = rb1[i];
    for (int i = tid; i < 2048; i += 128) sw2[i] = rw2[i];
    for (int i = tid; i < 64;   i += 128) sb2[i] = rb2[i];
    for (int i = tid; i < 4096; i += 128) sw3[i] = rw3[i];
    for (int i = tid; i < 64;   i += 128) sb3[i] = rb3[i];
    __syncthreads();

    const int item = blockIdx.x * 128 + tid;
    const int k = item & (KNN-1);
    const int n = (item >> 4) & (NPTS-1);
    const int b = item >> 16;
    const int j = g_idx[item];

    const float* pb = pos + (size_t)b * NPTS * 3;
    const float cx = pb[3*n], cy = pb[3*n+1], cz = pb[3*n+2];
    const float gx = pb[3*j], gy = pb[3*j+1], gz = pb[3*j+2];
    const float rx = gx - cx, ry = gy - cy, rz = gz - cz;
    const float s2 = rx*rx + ry*ry + rz*rz;
    const float dis = (s2 > 0.f) ? sqrtf(s2) : 0.f;

    const float f[10] = {cx, cy, cz, gx, gy, gz, rx, ry, rz, dis};

    const ulonglong2* w1q = (const ulonglong2*)sw1;   // 8 x 16B per input row
    const ulonglong2* w2q = (const ulonglong2*)sw2;   // 16 x 16B per input row
    const ulonglong2* w3q = (const ulonglong2*)sw3;   // 16 x 16B per input row

    // layer1: 10 -> 32, relu
    u64 h1p[16];
#pragma unroll
    for (int d = 0; d < 16; d++) h1p[d] = ((const u64*)sb1)[d];
#pragma unroll
    for (int c = 0; c < 10; c++) {
        const u64 aa = pk2(f[c]);
#pragma unroll
        for (int dq = 0; dq < 8; dq++) {
            const ulonglong2 ww = w1q[c*8 + dq];
            h1p[2*dq]   = fma2(aa, ww.x, h1p[2*dq]);
            h1p[2*dq+1] = fma2(aa, ww.y, h1p[2*dq+1]);
        }
    }
    float h1[32];
#pragma unroll
    for (int d = 0; d < 16; d++) {
        float2 t = upk(h1p[d]);
        h1[2*d]   = fmaxf(t.x, 0.f);
        h1[2*d+1] = fmaxf(t.y, 0.f);
    }

    // layer2: 32 -> 64, relu
    u64 h2p[32];
#pragma unroll
    for (int d = 0; d < 32; d++) h2p[d] = ((const u64*)sb2)[d];
#pragma unroll
    for (int c = 0; c < 32; c++) {
        const u64 aa = pk2(h1[c]);
#pragma unroll
        for (int dq = 0; dq < 16; dq++) {
            const ulonglong2 ww = w2q[c*16 + dq];
            h2p[2*dq]   = fma2(aa, ww.x, h2p[2*dq]);
            h2p[2*dq+1] = fma2(aa, ww.y, h2p[2*dq+1]);
        }
    }
    float h2[64];
#pragma unroll
    for (int d = 0; d < 32; d++) {
        float2 t = upk(h2p[d]);
        h2[2*d]   = fmaxf(t.x, 0.f);
        h2[2*d+1] = fmaxf(t.y, 0.f);
    }

    // layer3: 64 -> 64, no relu
    u64 wp[32];
#pragma unroll
    for (int d = 0; d < 32; d++) wp[d] = ((const u64*)sb3)[d];
#pragma unroll
    for (int c = 0; c < 64; c++) {
        const u64 aa = pk2(h2[c]);
#pragma unroll
        for (int dq = 0; dq < 16; dq++) {
            const ulonglong2 ww = w3q[c*16 + dq];
            wp[2*dq]   = fma2(aa, ww.x, wp[2*dq]);
            wp[2*dq+1] = fma2(aa, ww.y, wp[2*dq+1]);
        }
    }

    // weights * feat, warp max over k (16 lanes), relu, store (k==0 lane)
    const float* xr = x + ((size_t)b * NPTS + j) * CIN;
    float* outp = g_feat1 + ((size_t)b * NPTS + n) * INF;
#pragma unroll
    for (int d = 0; d < 32; d++) {
        const float2 t = upk(wp[d]);
        const int ch0 = 2*d, ch1 = 2*d + 1;
        float f0, f1;
        if (ch0 < CIN)       f0 = xr[ch0];
        else if (ch0 == 62)  f0 = gy;
        else                 f0 = gx;
        if (ch1 < CIN)       f1 = xr[ch1];
        else if (ch1 == 61)  f1 = gx;
        else                 f1 = gz;
        float v0 = t.x * f0;
        float v1 = t.y * f1;
#pragma unroll
        for (int off = 8; off >= 1; off >>= 1) {
            v0 = fmaxf(v0, __shfl_xor_sync(0xffffffffu, v0, off));
            v1 = fmaxf(v1, __shfl_xor_sync(0xffffffffu, v1, off));
        }
        if (k == 0) {
            outp[ch0] = fmaxf(v0, 0.f);
            outp[ch1] = fmaxf(v1, 0.f);
        }
    }
}

// ======== K3: GEMM1 [16384,64]@[64,128] + fb1, fused col-stats ==============
__global__ __launch_bounds__(256) void gemm1_kernel(
    const float* __restrict__ fw1, const float* __restrict__ fb1) {
    extern __shared__ float dyn[];
    float* sW    = dyn;                 // 64*128
    float* sAT   = dyn + 8192;          // 64*36
    float* sred  = dyn + 8192 + 2304;   // 8*128
    float* sqred = sred + 1024;
    const int tid = threadIdx.x;
    const int r0  = blockIdx.x * 32;

    for (int i = tid; i < 2048; i += 256)
        ((float4*)sW)[i] = ((const float4*)fw1)[i];
    for (int i = tid; i < 32*64; i += 256) {
        const int r = i >> 6, c = i & 63;
        sAT[c*36 + r] = g_feat1[(size_t)(r0 + r) * INF + c];
    }
    __syncthreads();

    const int cg = tid & 31;
    const int rg = tid >> 5;
    const float4 fb = reinterpret_cast<const float4*>(fb1)[cg];
    u64 accp[4][2];
#pragma unroll
    for (int i = 0; i < 4; i++) { accp[i][0] = pk(fb.x, fb.y); accp[i][1] = pk(fb.z, fb.w); }

    const ulonglong2* sWq = (const ulonglong2*)sW;
#pragma unroll 4
    for (int kk = 0; kk < 64; kk++) {
        const float4 a = *reinterpret_cast<const float4*>(&sAT[kk*36 + 4*rg]);
        const ulonglong2 ww = sWq[kk*32 + cg];
        const float av[4] = {a.x, a.y, a.z, a.w};
#pragma unroll
        for (int i = 0; i < 4; i++) {
            const u64 aa = pk2(av[i]);
            accp[i][0] = fma2(aa, ww.x, accp[i][0]);
            accp[i][1] = fma2(aa, ww.y, accp[i][1]);
        }
    }
    float s[4] = {0,0,0,0}, sq[4] = {0,0,0,0};
#pragma unroll
    for (int i = 0; i < 4; i++) {
        const float2 lo = upk(accp[i][0]), hi = upk(accp[i][1]);
        float4 o = make_float4(lo.x, lo.y, hi.x, hi.y);
        *reinterpret_cast<float4*>(&g_lin1[(size_t)(r0 + 4*rg + i) * OUTF + 4*cg]) = o;
        s[0] += o.x; s[1] += o.y; s[2] += o.z; s[3] += o.w;
        sq[0] = fmaf(o.x,o.x,sq[0]); sq[1] = fmaf(o.y,o.y,sq[1]);
        sq[2] = fmaf(o.z,o.z,sq[2]); sq[3] = fmaf(o.w,o.w,sq[3]);
    }
#pragma unroll
    for (int qq = 0; qq < 4; qq++) { sred[rg*128 + 4*cg + qq] = s[qq]; sqred[rg*128 + 4*cg + qq] = sq[qq]; }
    __syncthreads();
    if (tid < 128) {
        float a = 0.f, v = 0.f;
#pragma unroll
        for (int r = 0; r < 8; r++) { a += sred[r*128 + tid]; v += sqred[r*128 + tid]; }
        g_part[blockIdx.x*256 + tid]       = a;
        g_part[blockIdx.x*256 + 128 + tid] = v;
    }
}

// ==== K4: GEMM2 with BN1+relu on load, [16384,128]@[128,128]+fb2, stats =====
__global__ __launch_bounds__(256) void gemm2_kernel(
    const float* __restrict__ fw2, const float* __restrict__ fb2) {
    extern __shared__ float dyn[];
    float* sW    = dyn;                  // 128*128
    float* sAT   = dyn + 16384;          // 128*36
    float* sred  = dyn + 16384 + 4608;   // 8*128
    float* sqred = sred + 1024;
    const int tid = threadIdx.x;
    const int r0  = blockIdx.x * 32;

    for (int i = tid; i < 4096; i += 256)
        ((float4*)sW)[i] = ((const float4*)fw2)[i];
    const float* bn = g_bn;       // stage 0
    for (int i = tid; i < 32*128; i += 256) {
        const int r = i >> 7, c = i & 127;
        float v = g_lin1[(size_t)(r0 + r) * OUTF + c];
        v = fmaf(v, bn[c], bn[128 + c]);
        sAT[c*36 + r] = fmaxf(v, 0.f);
    }
    __syncthreads();

    const int cg = tid & 31;
    const int rg = tid >> 5;
    const float4 fb = reinterpret_cast<const float4*>(fb2)[cg];
    u64 accp[4][2];
#pragma unroll
    for (int i = 0; i < 4; i++) { accp[i][0] = pk(fb.x, fb.y); accp[i][1] = pk(fb.z, fb.w); }

    const ulonglong2* sWq = (const ulonglong2*)sW;
#pragma unroll 4
    for (int kk = 0; kk < 128; kk++) {
        const float4 a = *reinterpret_cast<const float4*>(&sAT[kk*36 + 4*rg]);
        const ulonglong2 ww = sWq[kk*32 + cg];
        const float av[4] = {a.x, a.y, a.z, a.w};
#pragma unroll
        for (int i = 0; i < 4; i++) {
            const u64 aa = pk2(av[i]);
            accp[i][0] = fma2(aa, ww.x, accp[i][0]);
            accp[i][1] = fma2(aa, ww.y, accp[i][1]);
        }
    }
    float s[4] = {0,0,0,0}, sq[4] = {0,0,0,0};
#pragma unroll
    for (int i = 0; i < 4; i++) {
        const float2 lo = upk(accp[i][0]), hi = upk(accp[i][1]);
        float4 o = make_float4(lo.x, lo.y, hi.x, hi.y);
        *reinterpret_cast<float4*>(&g_lin2[(size_t)(r0 + 4*rg + i) * OUTF + 4*cg]) = o;
        s[0] += o.x; s[1] += o.y; s[2] += o.z; s[3] += o.w;
        sq[0] = fmaf(o.x,o.x,sq[0]); sq[1] = fmaf(o.y,o.y,sq[1]);
        sq[2] = fmaf(o.z,o.z,sq[2]); sq[3] = fmaf(o.w,o.w,sq[3]);
    }
#pragma unroll
    for (int qq = 0; qq < 4; qq++) { sred[rg*128 + 4*cg + qq] = s[qq]; sqred[rg*128 + 4*cg + qq] = sq[qq]; }
    __syncthreads();
    if (tid < 128) {
        float a = 0.f, v = 0.f;
#pragma unroll
        for (int r = 0; r < 8; r++) { a += sred[r*128 + tid]; v += sqred[r*128 + tid]; }
        g_part[512*256 + blockIdx.x*256 + tid]       = a;
        g_part[512*256 + blockIdx.x*256 + 128 + tid] = v;
    }
}

// ======== finalize BN coefficients (parallelized: 1024 threads) =============
__global__ __launch_bounds__(1024) void finstats_kernel(
    int sel, const float* __restrict__ gamma, const float* __restrict__ beta) {
    __shared__ float red[4*256];
    __shared__ float tot[256];
    const float* part = g_part + sel * (512*256);
    float* bn = g_bn + sel * (2*OUTF);
    const int t = threadIdx.x;
    const int c = t & 255;
    const int g = t >> 8;
    float s = 0.f;
    const int rbeg = g * 128;
#pragma unroll 4
    for (int i = 0; i < 128; i++) s += part[(rbeg + i)*256 + c];
    red[g*256 + c] = s;
    __syncthreads();
    if (t < 256) tot[t] = (red[t] + red[256 + t]) + (red[512 + t] + red[768 + t]);
    __syncthreads();
    if (t < 128) {
        const float inv_n = 1.f / (float)NROW;
        const float m  = tot[t] * inv_n;
        const float v  = tot[128 + t] * inv_n - m * m;
        const float rs = rsqrtf(v + 1e-5f);
        const float a  = rs * gamma[t];
        bn[t]       = a;
        bn[128 + t] = beta[t] - m * a;
    }
}

// ===================== K7: final BN2 -> output (vectorized) =================
__global__ __launch_bounds__(1024) void final_kernel(float* __restrict__ out) {
    const int i = blockIdx.x * 1024 + threadIdx.x;   // 0..524287 (float4 units)
    const int c0 = (i << 2) & 127;
    const float* bn = g_bn + 2*OUTF;
    const float4 v = ((const float4*)g_lin2)[i];
    float4 o;
    o.x = fmaf(v.x, bn[c0],   bn[128 + c0]);
    o.y = fmaf(v.y, bn[c0+1], bn[128 + c0 + 1]);
    o.z = fmaf(v.z, bn[c0+2], bn[128 + c0 + 2]);
    o.w = fmaf(v.w, bn[c0+3], bn[128 + c0 + 3]);
    ((float4*)out)[i] = o;
}

// ============================================================================
extern "C" void kernel_launch(void* const* d_in, const int* in_sizes, int n_in,
                              void* d_out, int out_size) {
    (void)in_sizes; (void)n_in; (void)out_size;
    const float* x   = (const float*)d_in[0];
    const float* pos = (const float*)d_in[1];
    const float* rw1 = (const float*)d_in[2];
    const float* rb1 = (const float*)d_in[3];
    const float* rw2 = (const float*)d_in[4];
    const float* rb2 = (const float*)d_in[5];
    const float* rw3 = (const float*)d_in[6];
    const float* rb3 = (const float*)d_in[7];
    const float* fw1 = (const float*)d_in[8];
    const float* fb1 = (const float*)d_in[9];
    const float* g1  = (const float*)d_in[10];
    const float* b1  = (const float*)d_in[11];
    const float* fw2 = (const float*)d_in[12];
    const float* fb2 = (const float*)d_in[13];
    const float* g2  = (const float*)d_in[14];
    const float* b2  = (const float*)d_in[15];
    float* out = (float*)d_out;

    // 3 nops so the ncu capture (4th launch) lands on knn_kernel.
    nop_kernel<<<1, 32>>>();
    nop_kernel<<<1, 32>>>();
    nop_kernel<<<1, 32>>>();

    const int smem_knn = (NPTS*3 + NPTS + 2048 + 8 + 256 + 256 + 16 + 8) * 4;
    cudaFuncSetAttribute(knn_kernel, cudaFuncAttributeMaxDynamicSharedMemorySize, smem_knn);
    knn_kernel<<<2048, 256, smem_knn>>>(pos);

    relconv_kernel<<<NITEM/128, 128>>>(x, pos, rw1, rb1, rw2, rb2, rw3, rb3);

    const int smem1 = (8192 + 2304 + 2048) * 4;
    cudaFuncSetAttribute(gemm1_kernel, cudaFuncAttributeMaxDynamicSharedMemorySize, smem1);
    gemm1_kernel<<<NROW/32, 256, smem1>>>(fw1, fb1);
    finstats_kernel<<<1, 1024>>>(0, g1, b1);

    const int smem2 = (16384 + 4608 + 2048) * 4;
    cudaFuncSetAttribute(gemm2_kernel, cudaFuncAttributeMaxDynamicSharedMemorySize, smem2);
    gemm2_kernel<<<NROW/32, 256, smem2>>>(fw2, fb2);
    finstats_kernel<<<1, 1024>>>(1, g2, b2);

    final_kernel<<<524288/1024, 1024>>>(out);
}